// round 5
// baseline (speedup 1.0000x reference)
#include <cuda_runtime.h>

#define LEN     262144
#define NFFT    1024
#define STRIDE  256
#define HALF    512          // complex FFT size (real-packed)
#define CUT     513
#define NFRM    1029
#define NB      32
#define PLANE   16892064     // 32*513*1029

// Precomputed (double-precision accurate) tables
__device__ float2 g_tw[CUT];     // tw[j] = exp(-i*pi*j/512), j = 0..512
__device__ float  g_win[NFFT];   // Hann window

__global__ void init_tables() {
    int j = blockIdx.x * blockDim.x + threadIdx.x;
    if (j < CUT) {
        double s, c;
        sincospi(-(double)j / 512.0, &s, &c);   // exact at special angles
        float2 w = make_float2((float)c, (float)s);
        if (j == 512) w = make_float2(-1.0f, 0.0f);  // pin: X[512] purely real,
        if (j == 0)   w = make_float2( 1.0f, 0.0f);  // Xi must be exactly +0
        if (j == 256) w = make_float2( 0.0f, -1.0f);
        g_tw[j] = w;
    }
    if (j < NFFT) {
        double s, c;
        sincospi(2.0 * (double)j / (double)NFFT, &s, &c);
        g_win[j] = (float)(0.5 - 0.5 * c);
    }
}

__device__ __forceinline__ float2 cmul(float2 a, float2 b) {
    return make_float2(fmaf(a.x, b.x, -a.y*b.y), fmaf(a.x, b.y, a.y*b.x));
}
__device__ __forceinline__ float2 cadd(float2 a, float2 b) { return make_float2(a.x+b.x, a.y+b.y); }
__device__ __forceinline__ float2 csub(float2 a, float2 b) { return make_float2(a.x-b.x, a.y-b.y); }

// One 128-thread block per (frame t, batch b).
// Pack 1024 real windowed samples -> 512 complex, Stockham FFT-512
// (4 radix-4 stages + 1 radix-2 stage, autosorting), then real-FFT untangle.
__global__ __launch_bounds__(128) void stft_kernel(const float* __restrict__ x,
                                                   float* __restrict__ out) {
    __shared__ float2 bufA[HALF];
    __shared__ float2 bufB[HALF];
    __shared__ float2 tw[CUT];

    const int tid = threadIdx.x;      // 0..127
    const int t   = blockIdx.x;       // frame 0..1028
    const int b   = blockIdx.y;       // batch 0..31

    // Copy accurate twiddle table into smem (5 rounds: j=512 must be covered)
    #pragma unroll
    for (int r = 0; r < 5; r++) {
        int j = tid + r * 128;
        if (j < CUT) tw[j] = g_tw[j];
    }

    // ---- Load + Hann window + real->complex pack ----
    const float* xb = x + (size_t)b * LEN;
    const int start = t * STRIDE - NFFT;   // always even
    #pragma unroll
    for (int r = 0; r < 4; r++) {
        int n2 = tid + r * 128;            // 0..511
        int n0 = 2 * n2;
        int i0 = start + n0;               // even
        float2 v = make_float2(0.f, 0.f);
        if (i0 >= 0 && i0 < LEN) v = *(const float2*)(xb + i0);  // pair never straddles
        float w0 = g_win[n0];
        float w1 = g_win[n0 + 1];
        bufA[n2] = make_float2(v.x * w0, v.y * w1);
    }
    __syncthreads();

    // ---- Stockham FFT-512: 4 radix-4 stages (n = 512,128,32,8) ----
    float2* src = bufA;
    float2* dst = bufB;
    #pragma unroll
    for (int st = 0; st < 4; st++) {
        const int m      = (512 >> (2 * st)) >> 2;
        const int sshift = 2 * st;                 // s = 1 << sshift
        const int i = tid;                         // 0..127 = m*s butterflies
        const int p = i >> sshift;                 // [0, m)
        const int q = i & ((1 << sshift) - 1);     // [0, s)

        float2 a  = src[q + ((p        ) << sshift)];
        float2 bb = src[q + ((p +   m  ) << sshift)];
        float2 c  = src[q + ((p + 2*m  ) << sshift)];
        float2 d  = src[q + ((p + 3*m  ) << sshift)];

        // w1 = exp(-2*pi*i*p/n) = tw[p * 1024/n]; 1024/n = 2 << sshift
        float2 w1 = tw[p << (sshift + 1)];
        float2 w2 = cmul(w1, w1);
        float2 w3 = cmul(w1, w2);

        float2 apc  = cadd(a, c);
        float2 amc  = csub(a, c);
        float2 bpd  = cadd(bb, d);
        float2 jbmd = make_float2(d.y - bb.y, bb.x - d.x);   // i*(b-d)

        dst[q + ((4*p + 0) << sshift)] = cadd(apc, bpd);
        dst[q + ((4*p + 1) << sshift)] = cmul(w1, csub(amc, jbmd));
        dst[q + ((4*p + 2) << sshift)] = cmul(w2, csub(apc, bpd));
        dst[q + ((4*p + 3) << sshift)] = cmul(w3, cadd(amc, jbmd));
        __syncthreads();
        float2* tmp = src; src = dst; dst = tmp;
    }

    // ---- Final radix-2 stage (n = 2, s = 256) ----
    #pragma unroll
    for (int r = 0; r < 2; r++) {
        int q = tid + r * 128;            // 0..255
        float2 a  = src[q];
        float2 bb = src[q + 256];
        dst[q]       = cadd(a, bb);
        dst[q + 256] = csub(a, bb);
    }
    __syncthreads();
    const float2* Z = dst;   // natural-order FFT-512 of packed signal

    // ---- Real-FFT untangle + mag/angle + store ----
    float* __restrict__ mag_out = out;
    float* __restrict__ ang_out = out + PLANE;
    for (int k = tid; k < CUT; k += 128) {
        float2 A  = Z[k & 511];             // k = 512 wraps to Z[0]
        float2 Bc = Z[(512 - k) & 511];
        float Br = Bc.x, Bi = -Bc.y;        // conj
        float2 w = tw[k];                   // e^{-i pi k / 512}
        float sr = A.x + Br, si = A.y + Bi; // A + B
        float dr = A.x - Br, di = A.y - Bi; // A - B
        // X = 0.5*(A+B) - 0.5*i*w*(A-B)
        float Xr = 0.5f * (sr + fmaf(w.x, di,  w.y * dr));
        float Xi = 0.5f * (si - fmaf(w.x, dr, -w.y * di));

        float mag = sqrtf(fmaf(Xr, Xr, Xi * Xi));
        float ang = atan2f(Xi, Xr);

        size_t o = ((size_t)(b * CUT + k)) * NFRM + t;
        mag_out[o] = mag;
        ang_out[o] = ang;
    }
}

extern "C" void kernel_launch(void* const* d_in, const int* in_sizes, int n_in,
                              void* d_out, int out_size) {
    const float* x = (const float*)d_in[0];   // (32, 1, 262144) fp32
    float* out = (float*)d_out;               // mag plane then angle plane
    init_tables<<<(NFFT + 127) / 128, 128>>>();
    dim3 grid(NFRM, NB);
    stft_kernel<<<grid, 128>>>(x, out);
}

// round 6
// speedup vs baseline: 1.4021x; 1.4021x over previous
#include <cuda_runtime.h>

#define LEN     262144
#define NFFT    1024
#define STRIDE  256
#define HALF    512
#define CUT     513
#define NFRM    1029
#define NB      32
#define PLANE   16892064     // 32*513*1029
#define TB      4            // frames per block

// Precomputed (double-precision accurate) tables
__device__ float2 g_tw[CUT];     // tw[j] = exp(-i*pi*j/512)
__device__ float2 g_win2[HALF];  // Hann window, paired (2j, 2j+1)

__global__ void init_tables() {
    int j = blockIdx.x * blockDim.x + threadIdx.x;
    if (j < CUT) {
        double s, c;
        sincospi(-(double)j / 512.0, &s, &c);
        float2 w = make_float2((float)c, (float)s);
        if (j == 512) w = make_float2(-1.0f, 0.0f);  // pin: Xi[512] must be exactly +0
        if (j == 0)   w = make_float2( 1.0f, 0.0f);
        if (j == 256) w = make_float2( 0.0f, -1.0f);
        g_tw[j] = w;
    }
    if (j < HALF) {
        double s0, c0, s1, c1;
        sincospi(2.0 * (double)(2*j)     / (double)NFFT, &s0, &c0);
        sincospi(2.0 * (double)(2*j + 1) / (double)NFFT, &s1, &c1);
        g_win2[j] = make_float2((float)(0.5 - 0.5*c0), (float)(0.5 - 0.5*c1));
    }
}

__device__ __forceinline__ float2 cmul(float2 a, float2 b) {
    return make_float2(fmaf(a.x, b.x, -a.y*b.y), fmaf(a.x, b.y, a.y*b.x));
}
__device__ __forceinline__ float2 cadd(float2 a, float2 b) { return make_float2(a.x+b.x, a.y+b.y); }
__device__ __forceinline__ float2 csub(float2 a, float2 b) { return make_float2(a.x-b.x, a.y-b.y); }

// 256 threads: two 128-thread halves each run one frame's FFT; 2 iterations -> TB=4
// frames per block. Untangle results staged in smem, stored coalesced along t.
__global__ __launch_bounds__(256) void stft_kernel(const float* __restrict__ x,
                                                   float* __restrict__ out) {
    __shared__ float2 tw[CUT];
    __shared__ float2 bufA[2][HALF];
    __shared__ float2 bufB[2][HALF];
    __shared__ float  stg[2][CUT * 5];   // [plane][k*5 + f], stride-5 rows (conflict-free)

    const int tid = threadIdx.x;
    const int sub = tid >> 7;        // 0/1: which concurrent frame
    const int lt  = tid & 127;
    const int t0  = blockIdx.x * TB;
    const int b   = blockIdx.y;

    #pragma unroll
    for (int r = 0; r < 3; r++) {
        int j = tid + r * 256;
        if (j < CUT) tw[j] = g_tw[j];
    }

    const float* xb = x + (size_t)b * LEN;

    for (int it = 0; it < 2; it++) {
        const int f = it * 2 + sub;
        const int t = t0 + f;
        const int start = t * STRIDE - NFFT;   // always even
        float2* A = bufA[sub];
        float2* B = bufB[sub];

        // ---- Load + Hann window + real->complex pack ----
        #pragma unroll
        for (int r = 0; r < 4; r++) {
            int n2 = lt + r * 128;             // 0..511
            int i0 = start + 2 * n2;
            float2 v = make_float2(0.f, 0.f);
            if (i0 >= 0 && i0 < LEN) v = *(const float2*)(xb + i0);
            float2 w = g_win2[n2];
            A[n2] = make_float2(v.x * w.x, v.y * w.y);
        }
        __syncthreads();

        // ---- Stockham FFT-512: 4 radix-4 stages ----
        float2* src = A;
        float2* dst = B;
        #pragma unroll
        for (int st = 0; st < 4; st++) {
            const int m      = (512 >> (2 * st)) >> 2;
            const int sshift = 2 * st;
            const int p = lt >> sshift;
            const int q = lt & ((1 << sshift) - 1);

            float2 a  = src[q + ((p        ) << sshift)];
            float2 bb = src[q + ((p +   m  ) << sshift)];
            float2 c  = src[q + ((p + 2*m  ) << sshift)];
            float2 d  = src[q + ((p + 3*m  ) << sshift)];

            float2 w1 = tw[p << (sshift + 1)];
            float2 w2 = cmul(w1, w1);
            float2 w3 = cmul(w1, w2);

            float2 apc  = cadd(a, c);
            float2 amc  = csub(a, c);
            float2 bpd  = cadd(bb, d);
            float2 jbmd = make_float2(d.y - bb.y, bb.x - d.x);   // i*(b-d)

            dst[q + ((4*p + 0) << sshift)] = cadd(apc, bpd);
            dst[q + ((4*p + 1) << sshift)] = cmul(w1, csub(amc, jbmd));
            dst[q + ((4*p + 2) << sshift)] = cmul(w2, csub(apc, bpd));
            dst[q + ((4*p + 3) << sshift)] = cmul(w3, cadd(amc, jbmd));
            __syncthreads();
            float2* tmp = src; src = dst; dst = tmp;
        }
        // after 4 swaps: src == A holds the pre-radix-2 data.
        // Final radix-2 merged into untangle: Z(j) = s[j&255] +/- s[(j&255)+256]

        // ---- Untangle + mag/angle -> staging ----
        #pragma unroll
        for (int r = 0; r < 5; r++) {
            int k = lt + r * 128;
            if (k < CUT) {
                int j1 = k & 511;
                int j2 = (512 - k) & 511;
                float2 a1 = src[j1 & 255], b1 = src[(j1 & 255) + 256];
                float2 a2 = src[j2 & 255], b2 = src[(j2 & 255) + 256];
                float s1 = (j1 < 256) ? 1.f : -1.f;
                float s2 = (j2 < 256) ? 1.f : -1.f;
                float2 ZA = make_float2(fmaf(s1, b1.x, a1.x), fmaf(s1, b1.y, a1.y));
                float2 ZB = make_float2(fmaf(s2, b2.x, a2.x), fmaf(s2, b2.y, a2.y));
                float Br = ZB.x, Bi = -ZB.y;          // conj
                float2 w = tw[k];
                float sr = ZA.x + Br, si = ZA.y + Bi;
                float dr = ZA.x - Br, di = ZA.y - Bi;
                float Xr = 0.5f * (sr + fmaf(w.x, di,  w.y * dr));
                float Xi = 0.5f * (si - fmaf(w.x, dr, -w.y * di));

                stg[0][k * 5 + f] = sqrtf(fmaf(Xr, Xr, Xi * Xi));
                stg[1][k * 5 + f] = atan2f(Xi, Xr);
            }
        }
        __syncthreads();   // staging written; A free for next iteration
    }

    // ---- Coalesced store: runs of TB=4 contiguous t per k-row ----
    float* __restrict__ mag_out = out;
    float* __restrict__ ang_out = out + PLANE;
    for (int i = tid; i < CUT * TB; i += 256) {
        int k = i >> 2;
        int f = i & 3;
        int t = t0 + f;
        if (t < NFRM) {
            size_t o = ((size_t)(b * CUT + k)) * NFRM + t;
            mag_out[o] = stg[0][k * 5 + f];
            ang_out[o] = stg[1][k * 5 + f];
        }
    }
}

extern "C" void kernel_launch(void* const* d_in, const int* in_sizes, int n_in,
                              void* d_out, int out_size) {
    const float* x = (const float*)d_in[0];   // (32, 1, 262144) fp32
    float* out = (float*)d_out;               // mag plane then angle plane
    init_tables<<<(NFFT + 127) / 128, 128>>>();
    dim3 grid((NFRM + TB - 1) / TB, NB);      // 258 x 32
    stft_kernel<<<grid, 256>>>(x, out);
}

// round 7
// speedup vs baseline: 1.8072x; 1.2889x over previous
#include <cuda_runtime.h>

#define LEN     262144
#define NFFT    1024
#define STRIDE  256
#define HALF    512
#define CUT     513
#define NFRM    1029
#define NB      32
#define PLANE   16892064     // 32*513*1029
#define TB      4            // frames per block

// DP-accurate tables in global memory (small, L1/L2-hot)
__device__ float2 g_tw[CUT];      // W_1024^j, j=0..512 (untangle + copy to smem)
__device__ float2 g_win2[HALF];   // Hann pairs (2j, 2j+1)
__device__ float2 g_T1[8 * 64];   // [ka][l]  = W_512^{l*ka}
__device__ float2 g_T2[8 * 8];    // [kc][n0] = W_64^{n0*kc}

__global__ void init_tables() {
    int j = blockIdx.x * blockDim.x + threadIdx.x;
    if (j < CUT) {
        double s, c;
        sincospi(-(double)j / 512.0, &s, &c);
        float2 w = make_float2((float)c, (float)s);
        if (j == 512) w = make_float2(-1.0f, 0.0f);  // pin: Xi[512] exactly +0
        if (j == 0)   w = make_float2( 1.0f, 0.0f);
        if (j == 256) w = make_float2( 0.0f, -1.0f);
        g_tw[j] = w;
    }
    if (j < HALF) {
        double s0, c0, s1, c1;
        sincospi(2.0 * (double)(2*j)     / (double)NFFT, &s0, &c0);
        sincospi(2.0 * (double)(2*j + 1) / (double)NFFT, &s1, &c1);
        g_win2[j] = make_float2((float)(0.5 - 0.5*c0), (float)(0.5 - 0.5*c1));
    }
    if (j < 8 * 64) {
        int ka = j >> 6, l = j & 63;
        double s, c;
        sincospi(-(double)(l * ka) / 256.0, &s, &c);   // W_512^{l*ka}
        g_T1[j] = make_float2((float)c, (float)s);
    }
    if (j < 8 * 8) {
        int kc = j >> 3, n0 = j & 7;
        double s, c;
        sincospi(-(double)(n0 * kc) / 32.0, &s, &c);   // W_64^{n0*kc}
        g_T2[j] = make_float2((float)c, (float)s);
    }
}

__device__ __forceinline__ float2 cmul(float2 a, float2 b) {
    return make_float2(fmaf(a.x, b.x, -a.y*b.y), fmaf(a.x, b.y, a.y*b.x));
}
__device__ __forceinline__ float2 cadd(float2 a, float2 b) { return make_float2(a.x+b.x, a.y+b.y); }
__device__ __forceinline__ float2 csub(float2 a, float2 b) { return make_float2(a.x-b.x, a.y-b.y); }

// y[r] = sum_j a[j] * W8^{j*r}  (full 8-pt DFT, even/odd decomposition)
__device__ __forceinline__ void dft8(const float2 a[8], float2 y[8]) {
    float2 e0 = cadd(a[0], a[4]), e1 = csub(a[0], a[4]);
    float2 f0 = cadd(a[2], a[6]), f1 = csub(a[2], a[6]);
    float2 g0 = cadd(a[1], a[5]), g1 = csub(a[1], a[5]);
    float2 h0 = cadd(a[3], a[7]), h1 = csub(a[3], a[7]);
    float2 E0 = cadd(e0, f0), E2 = csub(e0, f0);
    float2 E1 = make_float2(e1.x + f1.y, e1.y - f1.x);   // e1 - i*f1
    float2 E3 = make_float2(e1.x - f1.y, e1.y + f1.x);   // e1 + i*f1
    float2 O0 = cadd(g0, h0), O2 = csub(g0, h0);
    float2 O1 = make_float2(g1.x + h1.y, g1.y - h1.x);
    float2 O3 = make_float2(g1.x - h1.y, g1.y + h1.x);
    const float C = 0.70710678118654752440f;
    float2 t1 = make_float2(C*(O1.x + O1.y), C*(O1.y - O1.x));    // W8^1*O1
    float2 t2 = make_float2(O2.y, -O2.x);                          // -i*O2
    float2 t3 = make_float2(C*(O3.y - O3.x), -C*(O3.x + O3.y));   // W8^3*O3
    y[0] = cadd(E0, O0); y[4] = csub(E0, O0);
    y[1] = cadd(E1, t1); y[5] = csub(E1, t1);
    y[2] = cadd(E2, t2); y[6] = csub(E2, t2);
    y[3] = cadd(E3, t3); y[7] = csub(E3, t3);
}

// 256 threads = 4 frames x 64 lanes. Register radix-8^3 FFT, 2 conflict-free
// smem exchanges, conjugate untangle, transposed staging store.
__global__ __launch_bounds__(256) void stft_kernel(const float* __restrict__ x,
                                                   float* __restrict__ out) {
    __shared__ float2 tw[CUT];            // 4104 B
    __shared__ float  fbuf[TB][1152];     // 4 x 4608 B (exchange / Z planes, aliased)
    __shared__ float  stg[2][CUT * 5];    // 20520 B

    const int tid = threadIdx.x;
    const int f   = tid >> 6;        // frame within block
    const int l   = tid & 63;        // lane within frame
    const int t0  = blockIdx.x * TB;
    const int b   = blockIdx.y;
    const int t   = t0 + f;

    for (int r = tid; r < CUT; r += 256) tw[r] = g_tw[r];

    float*  base = fbuf[f];
    float2* b2   = (float2*)base;

    // ---- Pass 1: load (global->regs, windowed, packed), radix-8 over n2 ----
    const float* xb = x + (size_t)b * LEN;
    const int start = t * STRIDE - NFFT;      // always even
    float2 a[8], y[8];
    #pragma unroll
    for (int j = 0; j < 8; j++) {
        int n  = l + 64 * j;                  // packed complex index
        int i0 = start + 2 * n;
        float2 v = make_float2(0.f, 0.f);
        if (i0 >= 0 && i0 < LEN) v = *(const float2*)(xb + i0);
        float2 w = g_win2[n];
        a[j] = make_float2(v.x * w.x, v.y * w.y);
    }
    dft8(a, y);
    #pragma unroll
    for (int ka = 1; ka < 8; ka++) y[ka] = cmul(y[ka], g_T1[ka * 64 + l]);
    {   // exchange 1 write: idx = 72*n1 + n0 + 8*ka  (conflict-free)
        int n0 = l & 7, n1 = l >> 3;
        #pragma unroll
        for (int ka = 0; ka < 8; ka++) b2[72 * n1 + n0 + 8 * ka] = y[ka];
    }
    __syncthreads();

    // ---- Pass 2: thread (n0, ka), radix-8 over n1 ----
    {
        int n0 = l & 7, ka = l >> 3;
        #pragma unroll
        for (int n1 = 0; n1 < 8; n1++) a[n1] = b2[72 * n1 + n0 + 8 * ka];
        dft8(a, y);
        #pragma unroll
        for (int kc = 1; kc < 8; kc++) y[kc] = cmul(y[kc], g_T2[kc * 8 + n0]);
        __syncthreads();   // reads complete before aliased overwrite
        #pragma unroll
        for (int kc = 0; kc < 8; kc++) b2[65 * n0 + kc + 8 * ka] = y[kc];
    }
    __syncthreads();

    // ---- Pass 3: thread (kc, ka), radix-8 over n0; X[ka + 8kc + 64kd] ----
    {
        int kc = l & 7, ka = l >> 3;
        #pragma unroll
        for (int n0 = 0; n0 < 8; n0++) a[n0] = b2[65 * n0 + kc + 8 * ka];
        dft8(a, y);
        __syncthreads();   // reads complete before aliased Z write
        float* zre = base;
        float* zim = base + 576;
        #pragma unroll
        for (int kd = 0; kd < 8; kd++) {
            int k  = ka + 8 * kc + 64 * kd;
            int zi = k + 4 * (k >> 5);        // conflict-free scalar layout
            zre[zi] = y[kd].x;
            zim[zi] = y[kd].y;
        }
    }
    __syncthreads();

    // ---- Real-FFT untangle + mag/angle -> staging ----
    {
        const float* zre = base;
        const float* zim = base + 576;
        #pragma unroll
        for (int r = 0; r < 9; r++) {
            int k = l + 64 * r;
            if (r == 8) { if (l != 0) break; k = 512; }
            int i1 = k & 511,         z1 = i1 + 4 * (i1 >> 5);
            int i2 = (512 - k) & 511, z2 = i2 + 4 * (i2 >> 5);
            float Ax = zre[z1], Ay = zim[z1];
            float Bx = zre[z2], By = -zim[z2];
            float2 w = tw[k];
            float sr = Ax + Bx, si = Ay + By;
            float dr = Ax - Bx, di = Ay - By;
            float Xr = 0.5f * (sr + fmaf(w.x, di,  w.y * dr));
            float Xi = 0.5f * (si - fmaf(w.x, dr, -w.y * di));
            stg[0][k * 5 + f] = sqrtf(fmaf(Xr, Xr, Xi * Xi));
            stg[1][k * 5 + f] = atan2f(Xi, Xr);
        }
    }
    __syncthreads();

    // ---- Coalesced store: runs of TB=4 contiguous t per k-row ----
    float* __restrict__ mag_out = out;
    float* __restrict__ ang_out = out + PLANE;
    for (int i = tid; i < CUT * TB; i += 256) {
        int k = i >> 2, ff = i & 3, tt = t0 + ff;
        if (tt < NFRM) {
            size_t o = ((size_t)(b * CUT + k)) * NFRM + tt;
            mag_out[o] = stg[0][k * 5 + ff];
            ang_out[o] = stg[1][k * 5 + ff];
        }
    }
}

extern "C" void kernel_launch(void* const* d_in, const int* in_sizes, int n_in,
                              void* d_out, int out_size) {
    const float* x = (const float*)d_in[0];   // (32, 1, 262144) fp32
    float* out = (float*)d_out;               // mag plane then angle plane
    init_tables<<<(NFFT + 127) / 128, 128>>>();
    dim3 grid((NFRM + TB - 1) / TB, NB);      // 258 x 32
    stft_kernel<<<grid, 256>>>(x, out);
}